// round 7
// baseline (speedup 1.0000x reference)
#include <cuda_runtime.h>
#include <cuda_bf16.h>
#include <math.h>

// Problem constants
#define NB     32
#define NPOLY  256
#define VPP    64
#define LDIM   32
#define V_TOT  (1 + NPOLY * VPP)   // 16385 rows per batch in `data`

// Scratch (device globals: no allocations allowed)
__device__ float g_P2[NB * NPOLY * 128];   // agg2 per (b, poly): P = [agg2, agg2]

// ---- packed f32x2 helpers (sm_103a dual-fp32 pipe; PTX-only) -------------
__device__ __forceinline__ unsigned long long pack2(float x, float y) {
    unsigned long long r;
    asm("mov.b64 %0, {%1, %2};" : "=l"(r) : "f"(x), "f"(y));
    return r;
}
__device__ __forceinline__ unsigned long long ffma2(unsigned long long a,
                                                    unsigned long long b,
                                                    unsigned long long c) {
    unsigned long long d;
    asm("fma.rn.f32x2 %0, %1, %2, %3;" : "=l"(d) : "l"(a), "l"(b), "l"(c));
    return d;
}
__device__ __forceinline__ float2 unpack2(unsigned long long v) {
    float2 f;
    asm("mov.b64 {%0, %1}, %2;" : "=f"(f.x), "=f"(f.y) : "l"(v));
    return f;
}

// ---------------------------------------------------------------------------
// Stage 1: per (b, poly) block — 3 x (GEMM + LayerNorm + ReLU + column max).
// x = concat([h, broadcast(agg)]) => per-row GEMM uses only the top CIN rows
// of W; the agg part folds into a per-block shared term. Only agg2 (128) is
// emitted: P = concat([agg2, agg2]).
//
// Serial-path design (R6):
//  - no smem atomics: per-warp col-max -> wmax[8][128]; warp0 reduces into
//    aggp while the other work of the staging phase proceeds (one sync).
//  - shared term k-split across 256/COUT threads per column (independent
//    LDGs, short chains); partials summed at accumulator init.
// ---------------------------------------------------------------------------
template<int CIN, int COUT, bool FIRST, bool LAST, int CPREV>
__device__ __forceinline__ void layer(
    const float* __restrict__ in_s,   // 64 x CIN (smem)
    float*       __restrict__ out_s,  // 64 x COUT (smem) or unused if LAST
    float*       __restrict__ Ws,     // smem weight buffer (CIN x COUT floats)
    const float* __restrict__ W,      // global weights ((CIN or 2*CIN) x COUT)
    const float* __restrict__ bias,
    const float* __restrict__ g,
    const float* __restrict__ beta,
    float*       __restrict__ aggp,   // smem: prev agg (CPREV), filled here
    float*       __restrict__ shsP,   // smem: 256 partial shared terms
    float*       __restrict__ wmax,   // smem: 8 x 128 per-warp col maxes
    int tid)
{
    constexpr int PC    = COUT / 32;   // columns per lane (1, 2, or 4)
    constexpr int SPLIT = 256 / COUT;  // threads per column for shared term
    constexpr int KCH   = CIN / SPLIT; // k-chunk per thread
    const int warp = tid >> 5, lane = tid & 31;
    const int rbase = warp * 8;        // this warp's 8 rows

    // Phase A: stage W_top (all threads) + warp0 reduces prev col-max -> aggp
    for (int i = tid; i < CIN * COUT / 4; i += 256)
        ((float4*)Ws)[i] = ((const float4*)W)[i];
    if (!FIRST && warp == 0) {
        #pragma unroll
        for (int c = lane; c < CPREV; c += 32) {
            float m = wmax[c];
            #pragma unroll
            for (int w = 1; w < 8; w++) m = fmaxf(m, wmax[w * 128 + c]);
            aggp[c] = m;
        }
    }
    __syncthreads();

    // Phase B: shared-term partials (k-split; all 256 threads busy)
    {
        const int c    = tid & (COUT - 1);
        const int part = tid >> (31 - __clz(COUT));   // tid / COUT
        float s = (part == 0) ? bias[c] : 0.f;
        if (!FIRST) {
            const float* wb = W + (size_t)(CIN + part * KCH) * COUT + c;
            const float* ap = aggp + part * KCH;
            #pragma unroll 8
            for (int kk = 0; kk < KCH; kk++)
                s = fmaf(ap[kk], wb[(size_t)kk * COUT], s);
        }
        shsP[part * COUT + c] = s;
    }
    __syncthreads();

    // Accumulator init = sum of SPLIT partials for this lane's columns
    float s0[PC];
    #pragma unroll
    for (int j = 0; j < PC; j++) {
        const int c = lane * PC + j;
        float t = shsP[c];
        #pragma unroll
        for (int part = 1; part < SPLIT; part++) t += shsP[part * COUT + c];
        s0[j] = t;
    }

    float gr[PC], br[PC], mx[PC];
    #pragma unroll
    for (int j = 0; j < PC; j++) {
        const int c = lane * PC + j;
        gr[j] = g[c]; br[j] = beta[c]; mx[j] = 0.f;
    }

    float vals[8][PC];   // post-GEMM values

    if constexpr (PC == 4) {
        unsigned long long acc[8][2];
        {
            const unsigned long long i0 = pack2(s0[0], s0[1]);
            const unsigned long long i1 = pack2(s0[2], s0[3]);
            #pragma unroll
            for (int r = 0; r < 8; r++) { acc[r][0] = i0; acc[r][1] = i1; }
        }
        for (int k0 = 0; k0 < CIN; k0 += 4) {
            unsigned long long w[4][2];
            #pragma unroll
            for (int kk = 0; kk < 4; kk++) {
                const ulonglong2 wv =
                    *(const ulonglong2*)(Ws + (k0 + kk) * COUT + lane * 4);
                w[kk][0] = wv.x; w[kk][1] = wv.y;
            }
            #pragma unroll
            for (int r = 0; r < 8; r++) {
                const float4 a = *(const float4*)(in_s + (rbase + r) * CIN + k0);
                unsigned long long ap;
                ap = pack2(a.x, a.x);
                acc[r][0] = ffma2(ap, w[0][0], acc[r][0]);
                acc[r][1] = ffma2(ap, w[0][1], acc[r][1]);
                ap = pack2(a.y, a.y);
                acc[r][0] = ffma2(ap, w[1][0], acc[r][0]);
                acc[r][1] = ffma2(ap, w[1][1], acc[r][1]);
                ap = pack2(a.z, a.z);
                acc[r][0] = ffma2(ap, w[2][0], acc[r][0]);
                acc[r][1] = ffma2(ap, w[2][1], acc[r][1]);
                ap = pack2(a.w, a.w);
                acc[r][0] = ffma2(ap, w[3][0], acc[r][0]);
                acc[r][1] = ffma2(ap, w[3][1], acc[r][1]);
            }
        }
        #pragma unroll
        for (int r = 0; r < 8; r++) {
            const float2 f0 = unpack2(acc[r][0]), f1 = unpack2(acc[r][1]);
            vals[r][0] = f0.x; vals[r][1] = f0.y; vals[r][2] = f1.x; vals[r][3] = f1.y;
        }
    } else if constexpr (PC == 2) {
        unsigned long long acc[8];
        {
            const unsigned long long i0 = pack2(s0[0], s0[1]);
            #pragma unroll
            for (int r = 0; r < 8; r++) acc[r] = i0;
        }
        for (int k0 = 0; k0 < CIN; k0 += 4) {
            unsigned long long w[4];
            #pragma unroll
            for (int kk = 0; kk < 4; kk++)
                w[kk] = *(const unsigned long long*)(Ws + (k0 + kk) * COUT + lane * 2);
            #pragma unroll
            for (int r = 0; r < 8; r++) {
                const float4 a = *(const float4*)(in_s + (rbase + r) * CIN + k0);
                acc[r] = ffma2(pack2(a.x, a.x), w[0], acc[r]);
                acc[r] = ffma2(pack2(a.y, a.y), w[1], acc[r]);
                acc[r] = ffma2(pack2(a.z, a.z), w[2], acc[r]);
                acc[r] = ffma2(pack2(a.w, a.w), w[3], acc[r]);
            }
        }
        #pragma unroll
        for (int r = 0; r < 8; r++) {
            const float2 f = unpack2(acc[r]);
            vals[r][0] = f.x; vals[r][1] = f.y;
        }
    } else {
        float acc[8];
        #pragma unroll
        for (int r = 0; r < 8; r++) acc[r] = s0[0];
        for (int k0 = 0; k0 < CIN; k0 += 4) {
            float w[4];
            #pragma unroll
            for (int kk = 0; kk < 4; kk++)
                w[kk] = Ws[(k0 + kk) * COUT + lane];
            #pragma unroll
            for (int r = 0; r < 8; r++) {
                const float4 a = *(const float4*)(in_s + (rbase + r) * CIN + k0);
                acc[r] = fmaf(a.x, w[0], acc[r]);
                acc[r] = fmaf(a.y, w[1], acc[r]);
                acc[r] = fmaf(a.z, w[2], acc[r]);
                acc[r] = fmaf(a.w, w[3], acc[r]);
            }
        }
        #pragma unroll
        for (int r = 0; r < 8; r++) vals[r][0] = acc[r];
    }

    // Per-row LayerNorm + ReLU + running column max
    #pragma unroll
    for (int r = 0; r < 8; r++) {
        float sum = 0.f, sq = 0.f;
        #pragma unroll
        for (int j = 0; j < PC; j++) { sum += vals[r][j]; sq += vals[r][j] * vals[r][j]; }
        #pragma unroll
        for (int o = 16; o > 0; o >>= 1) {
            sum += __shfl_xor_sync(0xffffffffu, sum, o);
            sq  += __shfl_xor_sync(0xffffffffu, sq,  o);
        }
        const float mu  = sum * (1.0f / COUT);
        const float var = fmaxf(sq * (1.0f / COUT) - mu * mu, 0.f);
        const float inv = rsqrtf(var + 1e-5f);
        float v[PC];
        #pragma unroll
        for (int j = 0; j < PC; j++) {
            v[j] = fmaxf(fmaf(gr[j] * (vals[r][j] - mu), inv, br[j]), 0.f);
            mx[j] = fmaxf(mx[j], v[j]);
        }
        if (!LAST) {
            if constexpr (PC == 4)
                *(float4*)(out_s + (rbase + r) * COUT + lane * 4) =
                    make_float4(v[0], v[1], v[2], v[3]);
            else if constexpr (PC == 2)
                *(float2*)(out_s + (rbase + r) * COUT + lane * 2) =
                    make_float2(v[0], v[1]);
            else
                out_s[(rbase + r) * COUT + lane] = v[0];
        }
    }
    // Per-warp column max -> wmax[warp][*] (no atomics; each warp owns a row)
    if constexpr (PC == 4)
        *(float4*)(wmax + warp * 128 + lane * 4) = make_float4(mx[0], mx[1], mx[2], mx[3]);
    else if constexpr (PC == 2)
        *(float2*)(wmax + warp * 128 + lane * 2) = make_float2(mx[0], mx[1]);
    else
        wmax[warp * 128 + lane] = mx[0];
    __syncthreads();
}

__global__ void __launch_bounds__(256, 3) stage1_kernel(
    const float* __restrict__ data,
    const float* __restrict__ W0, const float* __restrict__ b0,
    const float* __restrict__ g0, const float* __restrict__ be0,
    const float* __restrict__ W1, const float* __restrict__ b1,
    const float* __restrict__ g1, const float* __restrict__ be1,
    const float* __restrict__ W2, const float* __restrict__ b2,
    const float* __restrict__ g2, const float* __restrict__ be2)
{
    extern __shared__ float smem[];
    // Layout (13696 floats = 53.5 KB; 3 CTAs/SM fit in 228 KB):
    float* bufA = smem;                  // 64*64 (x 64x32, later h1 64x64)
    float* Ws   = bufA + 64 * 64;        // 64*128 weight tile
    float* bufB = Ws + 4096;             // h0 (64x32) aliases Ws[4096..6143]:
                                         // layer1 stages Ws[0..1023], layer2
                                         // Ws[0..2047]; layer3 staging clobbers
                                         // only after h0 is dead (sync-fenced).
    float* wmax = Ws + 64 * 128;         // 8*128 per-warp col maxes
    float* aggp = wmax + 8 * 128;        // 128
    float* shsP = aggp + 128;            // 256 partial shared terms

    const int tid = threadIdx.x;
    const int blk = blockIdx.x;          // b*NPOLY + p
    const int b = blk >> 8, p = blk & 255;

    // Load x tile (64 x 32), zero channel 31 (vecs[:, :, -1] = 0)
    const float* src = data + (size_t)b * V_TOT * LDIM + LDIM + (size_t)p * VPP * LDIM;
    for (int i = tid; i < 64 * 32; i += 256) {
        float v = src[i];
        if ((i & 31) == 31) v = 0.f;
        bufA[i] = v;
    }
    __syncthreads();

    layer<32, 32,  true,  false, 32>(bufA, bufB, Ws, W0, b0, g0, be0, aggp, shsP, wmax, tid);
    layer<32, 64,  false, false, 32>(bufB, bufA, Ws, W1, b1, g1, be1, aggp, shsP, wmax, tid);
    layer<64, 128, false, true,  64>(bufA, nullptr, Ws, W2, b2, g2, be2, aggp, shsP, wmax, tid);

    // Final reduction of layer-3 per-warp maxes -> P2
    if (tid < 128) {
        float m = wmax[tid];
        #pragma unroll
        for (int w = 1; w < 8; w++) m = fmaxf(m, wmax[w * 128 + tid]);
        g_P2[(size_t)blk * 128 + tid] = m;
    }
}

// ---------------------------------------------------------------------------
// Stage 2: attention, algebraically reduced, with W-folding fused in.
// One block per batch.  (P = [agg2, agg2] => W_eff = W[:128] + W[128:].)
//   q = P2[b, aid] @ Wq_eff + bq
//   t = Wk_eff @ q            (scores = P2 . t / 16 + const; const cancels)
//   att = softmax(scores)
//   out = (sum_p att_p * P2[b,p]) @ Wv_eff + bv
// ---------------------------------------------------------------------------
__global__ void __launch_bounds__(256) attn_kernel(
    const float* __restrict__ data,
    const float* __restrict__ Wq, const float* __restrict__ bq,
    const float* __restrict__ Wk,
    const float* __restrict__ Wv, const float* __restrict__ bv,
    float* __restrict__ out)
{
    __shared__ float ps[128], qs[256], ts[128], att[256], pbar[128], red[256];
    const int b = blockIdx.x, tid = threadIdx.x;

    const int aid = (int)data[(size_t)b * V_TOT * LDIM];   // data[b][0][0]
    if (tid < 128) ps[tid] = g_P2[((size_t)b * NPOLY + aid) * 128 + tid];
    __syncthreads();

    // q[c] (fold Wq halves on the fly)
    {
        float acc = bq[tid];
        #pragma unroll 4
        for (int j = 0; j < 128; j++)
            acc = fmaf(ps[j], Wq[j * 256 + tid] + Wq[(j + 128) * 256 + tid], acc);
        qs[tid] = acc;
    }
    __syncthreads();

    // t[j] = sum_c Wk_eff[j][c] * q[c]
    if (tid < 128) {
        float acc = 0.f;
        #pragma unroll 4
        for (int c = 0; c < 256; c++)
            acc = fmaf(Wk[tid * 256 + c] + Wk[(tid + 128) * 256 + c], qs[c], acc);
        ts[tid] = acc;
    }
    __syncthreads();

    // scores (per poly p = tid)
    float s = 0.f;
    {
        const float4* Pp = (const float4*)(g_P2 + ((size_t)b * NPOLY + tid) * 128);
        #pragma unroll 8
        for (int j = 0; j < 32; j++) {
            float4 pv = Pp[j];
            s = fmaf(pv.x, ts[4 * j + 0], s);
            s = fmaf(pv.y, ts[4 * j + 1], s);
            s = fmaf(pv.z, ts[4 * j + 2], s);
            s = fmaf(pv.w, ts[4 * j + 3], s);
        }
        s *= 0.0625f;   // 1/sqrt(256)
    }
    // softmax over 256
    red[tid] = s; __syncthreads();
    for (int o = 128; o > 0; o >>= 1) {
        if (tid < o) red[tid] = fmaxf(red[tid], red[tid + o]);
        __syncthreads();
    }
    const float m = red[0]; __syncthreads();
    const float e = expf(s - m);
    red[tid] = e; __syncthreads();
    for (int o = 128; o > 0; o >>= 1) {
        if (tid < o) red[tid] += red[tid + o];
        __syncthreads();
    }
    att[tid] = e / red[0];
    __syncthreads();

    // pbar[j] = sum_p att[p] * P2[b,p,j]   (coalesced across tid=j)
    if (tid < 128) {
        float acc = 0.f;
        const float* Pb = g_P2 + (size_t)b * NPOLY * 128;
        for (int p = 0; p < 256; p++) acc = fmaf(att[p], Pb[p * 128 + tid], acc);
        pbar[tid] = acc;
    }
    __syncthreads();

    // out[c] (fold Wv halves on the fly)
    {
        float acc = bv[tid];
        #pragma unroll 4
        for (int j = 0; j < 128; j++)
            acc = fmaf(pbar[j], Wv[j * 256 + tid] + Wv[(j + 128) * 256 + tid], acc);
        out[b * 256 + tid] = acc;
    }
}

// ---------------------------------------------------------------------------
extern "C" void kernel_launch(void* const* d_in, const int* in_sizes, int n_in,
                              void* d_out, int out_size)
{
    const float* data = (const float*)d_in[0];
    const float* W0 = (const float*)d_in[1];
    const float* b0 = (const float*)d_in[2];
    const float* g0 = (const float*)d_in[3];
    const float* be0= (const float*)d_in[4];
    const float* W1 = (const float*)d_in[5];
    const float* b1 = (const float*)d_in[6];
    const float* g1 = (const float*)d_in[7];
    const float* be1= (const float*)d_in[8];
    const float* W2 = (const float*)d_in[9];
    const float* b2 = (const float*)d_in[10];
    const float* g2 = (const float*)d_in[11];
    const float* be2= (const float*)d_in[12];
    const float* Wq = (const float*)d_in[13];
    const float* bq = (const float*)d_in[14];
    const float* Wk = (const float*)d_in[15];
    const float* bk = (const float*)d_in[16];
    const float* Wv = (const float*)d_in[17];
    const float* bv = (const float*)d_in[18];
    float* out = (float*)d_out;
    (void)bk;

    const int smem_bytes = (64*64 + 64*128 + 8*128 + 128 + 256) * (int)sizeof(float);
    cudaFuncSetAttribute(stage1_kernel,
                         cudaFuncAttributeMaxDynamicSharedMemorySize, smem_bytes);

    stage1_kernel<<<NB * NPOLY, 256, smem_bytes>>>(
        data, W0, b0, g0, be0, W1, b1, g1, be1, W2, b2, g2, be2);
    attn_kernel<<<NB, 256>>>(data, Wq, bq, Wk, Wv, bv, out);
}